// round 4
// baseline (speedup 1.0000x reference)
#include <cuda_runtime.h>
#include <cuda_fp16.h>
#include <cstdint>

// Problem dims
#define NB   2048
#define ND   512
#define NH   64
#define NHID 2048

// Tiling
#define BM   256
#define BN   128
#define BK   64
#define NTHREADS 256
#define NSTAGE 4
#define NCHUNK 128          // 16 n-tiles * 8 k-tiles

// smem stage layout (bytes). A stored k-major: 64 k-rows x 512B (+16 pad).
// B k-major: 64 k-rows x 256B (+16 pad).
#define LDAT 528
#define LDBT 272
#define ASTG (64 * LDAT)                  // 33792
#define BSTG (64 * LDBT)                  // 17408
#define STG  (ASTG + BSTG)                // 51200
#define OFF_ROWACC (NSTAGE * STG)         // 204800
#define OFF_MBAR   (OFF_ROWACC + BM * 4)  // 205824
#define SMEM_DYN   (OFF_MBAR + 64)

#define STAGE_TX (64 * 512 + 64 * 256)    // 49152 bytes per stage

// fp16 copies (device globals; allocation-free)
__device__ __half g_Wh[(size_t)NH * ND * NHID];   // [H][D][HID], n contiguous
__device__ __half g_Xt[(size_t)ND * NB];          // [D][B] transposed, m contiguous

__device__ __forceinline__ uint32_t smem_u32(const void* p) {
    return (uint32_t)__cvta_generic_to_shared(p);
}
__device__ __forceinline__ float lrelu(float v) {
    return (v >= 0.f) ? v : 0.01f * v;
}
__device__ __forceinline__ void bulk_cp(uint32_t dst, const void* src,
                                        uint32_t bytes, uint32_t mbar) {
    asm volatile(
        "cp.async.bulk.shared::cta.global.mbarrier::complete_tx::bytes "
        "[%0], [%1], %2, [%3];"
        :: "r"(dst), "l"(src), "r"(bytes), "r"(mbar) : "memory");
}
__device__ __forceinline__ void mbar_init(uint32_t a, uint32_t cnt) {
    asm volatile("mbarrier.init.shared.b64 [%0], %1;" :: "r"(a), "r"(cnt) : "memory");
}
__device__ __forceinline__ void mbar_expect(uint32_t a, uint32_t tx) {
    asm volatile("mbarrier.arrive.expect_tx.shared::cta.b64 _, [%0], %1;"
                 :: "r"(a), "r"(tx) : "memory");
}
__device__ __forceinline__ void mbar_wait(uint32_t a, uint32_t parity) {
    asm volatile(
        "{\n\t.reg .pred P1;\n\t"
        "WAIT_%=: mbarrier.try_wait.parity.shared::cta.b64 P1, [%0], %1, 0x989680;\n\t"
        "@P1 bra.uni DONE_%=;\n\t"
        "bra.uni WAIT_%=;\n\t"
        "DONE_%=:\n\t}"
        :: "r"(a), "r"(parity) : "memory");
}

// ---------------------------------------------------------------------------
// Converts
// ---------------------------------------------------------------------------
__global__ void convert_w_kernel(const float* __restrict__ W1) {
    size_t i = (size_t)blockIdx.x * blockDim.x + threadIdx.x;
    const size_t n4 = (size_t)NH * ND * NHID / 4;
    if (i >= n4) return;
    float4 v = ((const float4*)W1)[i];
    __half2* d = (__half2*)g_Wh;
    d[2 * i]     = __floats2half2_rn(v.x, v.y);
    d[2 * i + 1] = __floats2half2_rn(v.z, v.w);
}

// transpose x [B][D] fp32 -> g_Xt [D][B] fp16
__global__ void convert_x_kernel(const float* __restrict__ X) {
    __shared__ float tile[32][33];
    int m0 = blockIdx.x * 32, k0 = blockIdx.y * 32;
    int tx = threadIdx.x, ty = threadIdx.y;     // 32 x 8
    #pragma unroll
    for (int i = 0; i < 4; i++)
        tile[ty + i * 8][tx] = X[(size_t)(m0 + ty + i * 8) * ND + k0 + tx];
    __syncthreads();
    #pragma unroll
    for (int i = 0; i < 4; i++) {
        int k = ty + i * 8;
        g_Xt[(size_t)(k0 + k) * NB + m0 + tx] = __float2half(tile[tx][k]);
    }
}

// ---------------------------------------------------------------------------
// Main fused kernel. CTA = (256-row m-tile, head). 8 warps in 4(M)x2(N),
// warp tile 64x64. cp.async.bulk staging (warp 0), 4-stage mbarrier pipeline,
// single __syncthreads per chunk. Epilogue fuses bias+leaky+dot(W2).
// ---------------------------------------------------------------------------
__global__ void __launch_bounds__(NTHREADS, 1)
mhmlp_main_kernel(const float* __restrict__ b1, const float* __restrict__ W2,
                  const float* __restrict__ b2, float* __restrict__ out)
{
    extern __shared__ char smem[];
    const uint32_t sbase = smem_u32(smem);
    float* rowacc = (float*)(smem + OFF_ROWACC);

    const int tid  = threadIdx.x;
    const int lane = tid & 31;
    const int wid  = tid >> 5;
    const int wm   = wid >> 1;      // 0..3 : 64-row band
    const int wn   = wid & 1;       // 0..1 : 64-col band

    const int mt = blockIdx.x;      // 8  (fast -> head weights hot in L2)
    const int h  = blockIdx.y;      // 64
    const int m0 = mt * BM;

    rowacc[tid] = 0.f;
    if (tid < NSTAGE) mbar_init(sbase + OFF_MBAR + tid * 8, 1);
    __syncthreads();

    const __half* __restrict__ Wh_h = g_Wh + (size_t)h * ND * NHID;
    const float* __restrict__ b1h = b1 + (size_t)h * NHID;
    const float* __restrict__ W2h = W2 + (size_t)h * NHID;

    // warp 0 stages chunk cc into stage s: 64 A rows (512B) + 64 B rows (256B)
    auto stage = [&](int s, int cc) {
        const int nt = cc >> 3, kt = cc & 7;
        const uint32_t sb = sbase + s * STG;
        const uint32_t bar = sbase + OFF_MBAR + s * 8;
        if (lane == 0) mbar_expect(bar, STAGE_TX);
        __syncwarp();
        #pragma unroll
        for (int i = 0; i < 4; i++) {
            int o = lane * 4 + i;            // 0..127
            if (o < 64) {                    // A row o: k = kt*64+o, 256 m
                const void* src = g_Xt + (size_t)(kt * BK + o) * NB + m0;
                bulk_cp(sb + o * LDAT, src, 512, bar);
            } else {                         // B row o-64
                int r = o - 64;
                const void* src = Wh_h + (size_t)(kt * BK + r) * NHID + nt * BN;
                bulk_cp(sb + ASTG + r * LDBT, src, 256, bar);
            }
        }
    };

    float c[4][8][4];
    #pragma unroll
    for (int mi = 0; mi < 4; mi++)
        #pragma unroll
        for (int ni = 0; ni < 8; ni++)
            #pragma unroll
            for (int e = 0; e < 4; e++) c[mi][ni][e] = 0.f;
    float accrow[8] = {0.f,0.f,0.f,0.f,0.f,0.f,0.f,0.f};

    if (wid == 0) { stage(0, 0); stage(1, 1); }

    for (int cc = 0; cc < NCHUNK; ++cc) {
        if (wid == 0 && cc + 2 < NCHUNK) stage((cc + 2) % NSTAGE, cc + 2);
        mbar_wait(sbase + OFF_MBAR + (cc % NSTAGE) * 8, (cc >> 2) & 1);
        __syncthreads();

        const uint32_t aB = sbase + (cc % NSTAGE) * STG;
        const uint32_t bB = aB + ASTG;

        #pragma unroll
        for (int ks = 0; ks < 4; ks++) {
            // A fragments via ldmatrix.trans on k-major A
            uint32_t a[4][4];
            #pragma unroll
            for (int mi = 0; mi < 4; mi++) {
                uint32_t ad = aB + (ks * 16 + (lane & 15)) * LDAT
                            + (wm * 64 + mi * 16 + (lane >> 4) * 8) * 2;
                uint32_t q0, q1, q2, q3;
                asm volatile(
                    "ldmatrix.sync.aligned.m8n8.x4.trans.shared.b16 {%0,%1,%2,%3}, [%4];"
                    : "=r"(q0), "=r"(q1), "=r"(q2), "=r"(q3) : "r"(ad));
                a[mi][0] = q0; a[mi][1] = q2; a[mi][2] = q1; a[mi][3] = q3;
            }
            uint32_t bf[8][2];
            #pragma unroll
            for (int np = 0; np < 4; np++) {
                uint32_t ad = bB + (ks * 16 + (lane & 15)) * LDBT
                            + (wn * 64 + np * 16 + (lane >> 4) * 8) * 2;
                uint32_t r0, r1, r2, r3;
                asm volatile(
                    "ldmatrix.sync.aligned.m8n8.x4.trans.shared.b16 {%0,%1,%2,%3}, [%4];"
                    : "=r"(r0), "=r"(r1), "=r"(r2), "=r"(r3) : "r"(ad));
                bf[2 * np][0] = r0;     bf[2 * np][1] = r1;
                bf[2 * np + 1][0] = r2; bf[2 * np + 1][1] = r3;
            }
            #pragma unroll
            for (int mi = 0; mi < 4; mi++)
                #pragma unroll
                for (int ni = 0; ni < 8; ni++) {
                    asm volatile(
                        "mma.sync.aligned.m16n8k16.row.col.f32.f16.f16.f32 "
                        "{%0,%1,%2,%3}, {%4,%5,%6,%7}, {%8,%9}, {%0,%1,%2,%3};"
                        : "+f"(c[mi][ni][0]), "+f"(c[mi][ni][1]),
                          "+f"(c[mi][ni][2]), "+f"(c[mi][ni][3])
                        : "r"(a[mi][0]), "r"(a[mi][1]), "r"(a[mi][2]), "r"(a[mi][3]),
                          "r"(bf[ni][0]), "r"(bf[ni][1]));
                }
        }

        if ((cc & 7) == 7) {   // K done for this n-tile -> fused epilogue
            const int nt = cc >> 3;
            #pragma unroll
            for (int mi = 0; mi < 4; mi++)
                #pragma unroll
                for (int ni = 0; ni < 8; ni++)
                    #pragma unroll
                    for (int e = 0; e < 4; e++) {
                        int col = nt * BN + wn * 64 + ni * 8 + (lane & 3) * 2 + (e & 1);
                        float p = c[mi][ni][e] + __ldg(&b1h[col]);
                        accrow[mi * 2 + (e >> 1)] = fmaf(lrelu(p), __ldg(&W2h[col]),
                                                         accrow[mi * 2 + (e >> 1)]);
                        c[mi][ni][e] = 0.f;
                    }
        }
    }

    // reduce 4 lanes sharing each row, then across wn via smem atomics
    #pragma unroll
    for (int off = 1; off <= 2; off <<= 1)
        #pragma unroll
        for (int j = 0; j < 8; j++)
            accrow[j] += __shfl_xor_sync(0xffffffffu, accrow[j], off);

    if ((lane & 3) == 0) {
        #pragma unroll
        for (int mi = 0; mi < 4; mi++)
            #pragma unroll
            for (int e2 = 0; e2 < 2; e2++) {
                int row = wm * 64 + mi * 16 + e2 * 8 + (lane >> 2);
                atomicAdd(&rowacc[row], accrow[mi * 2 + e2]);
            }
    }
    __syncthreads();
    {
        float v = rowacc[tid] + __ldg(&b2[h]);
        out[(size_t)(m0 + tid) * NH + h] = lrelu(v);
    }
}

// ---------------------------------------------------------------------------
extern "C" void kernel_launch(void* const* d_in, const int* in_sizes, int n_in,
                              void* d_out, int out_size) {
    const float* x  = (const float*)d_in[0];   // [2048, 512]
    const float* W1 = (const float*)d_in[1];   // [64, 512, 2048]
    const float* b1 = (const float*)d_in[2];   // [64, 2048]
    const float* W2 = (const float*)d_in[3];   // [64, 2048]
    const float* b2 = (const float*)d_in[4];   // [64]
    float* out = (float*)d_out;                // [2048, 64]
    (void)in_sizes; (void)n_in; (void)out_size;

    cudaFuncSetAttribute(mhmlp_main_kernel,
                         cudaFuncAttributeMaxDynamicSharedMemorySize, SMEM_DYN);

    {
        size_t n4 = (size_t)NH * ND * NHID / 4;
        convert_w_kernel<<<(int)((n4 + 255) / 256), 256>>>(W1);
    }
    {
        dim3 g(NB / 32, ND / 32);
        convert_x_kernel<<<g, dim3(32, 8)>>>(x);
    }

    dim3 grid(NB / BM, NH);
    mhmlp_main_kernel<<<grid, NTHREADS, SMEM_DYN>>>(b1, W2, b2, out);
}

// round 6
// speedup vs baseline: 3.7290x; 3.7290x over previous
#include <cuda_runtime.h>
#include <cuda_fp16.h>
#include <cstdint>

// Problem dims
#define NB   2048
#define ND   512
#define NH   64
#define NHID 2048

// Tiling
#define BM   128
#define BN   256
#define BK   64
#define NTHREADS 512
#define NCHUNK 64            // 8 n-tiles * 8 k-tiles

// smem layout (bytes)
// A: 128 rows x 512 halves, padded stride 520 halves (1040 B) -> conflict-free
#define LDAF_B 1040
#define OFF_A  0
#define ASZ    (BM * LDAF_B)              // 133120
// B: 3 stages, each 64 k-rows x 256 halves = 32768 B, XOR-swizzled (no pad)
#define OFF_B  ASZ
#define BSTG   32768
#define NSTAGE 3
#define OFF_ROWACC (OFF_B + NSTAGE * BSTG)   // 231424
#define SMEM_DYN   (OFF_ROWACC + BM * 4)     // 231936

// fp16 copies + packed epilogue params (device globals; allocation-free)
__device__ __half g_Wh[(size_t)NH * ND * NHID];   // [H][D][HID], n contiguous
__device__ __half g_Xh[(size_t)NB * ND];          // [B][D], k contiguous
__device__ float4 g_pk4[(size_t)NH * (NHID / 2)]; // (b1[2c],b1[2c+1],W2[2c],W2[2c+1])

__device__ __forceinline__ uint32_t smem_u32(const void* p) {
    return (uint32_t)__cvta_generic_to_shared(p);
}
__device__ __forceinline__ void cp16(uint32_t dst, const void* src) {
    asm volatile("cp.async.cg.shared.global [%0], [%1], 16;" :: "r"(dst), "l"(src));
}
__device__ __forceinline__ void cp_commit() {
    asm volatile("cp.async.commit_group;" ::: "memory");
}
__device__ __forceinline__ float lrelu(float v) {
    return (v >= 0.f) ? v : 0.01f * v;
}

// ---------------------------------------------------------------------------
// Converts
// ---------------------------------------------------------------------------
__global__ void convert_w_kernel(const float* __restrict__ W1) {
    size_t i = (size_t)blockIdx.x * blockDim.x + threadIdx.x;
    const size_t n4 = (size_t)NH * ND * NHID / 4;
    if (i >= n4) return;
    float4 v = ((const float4*)W1)[i];
    __half2* d = (__half2*)g_Wh;
    d[2 * i]     = __floats2half2_rn(v.x, v.y);
    d[2 * i + 1] = __floats2half2_rn(v.z, v.w);
}
__global__ void convert_x_kernel(const float* __restrict__ X) {
    size_t i = (size_t)blockIdx.x * blockDim.x + threadIdx.x;
    const size_t n4 = (size_t)NB * ND / 4;
    if (i >= n4) return;
    float4 v = ((const float4*)X)[i];
    __half2* d = (__half2*)g_Xh;
    d[2 * i]     = __floats2half2_rn(v.x, v.y);
    d[2 * i + 1] = __floats2half2_rn(v.z, v.w);
}
__global__ void pack_kernel(const float* __restrict__ b1, const float* __restrict__ W2) {
    int i = blockIdx.x * blockDim.x + threadIdx.x;     // 64 * 1024
    if (i >= NH * (NHID / 2)) return;
    int h = i >> 10, c = i & 1023;
    const float* b = b1 + (size_t)h * NHID + 2 * c;
    const float* w = W2 + (size_t)h * NHID + 2 * c;
    g_pk4[i] = make_float4(b[0], b[1], w[0], w[1]);
}

// ---------------------------------------------------------------------------
// Main fused kernel. CTA = (128-row m-tile, head). A resident in smem; B
// streamed through a 3-stage cp.async pipeline. TWO barriers per chunk:
// the trailing one fences ldmatrix reads of chunk cc before any warp can
// issue stageB(cc+3) into the same buffer (the R5 race).
// 16 warps in 4(M)x4(N); warp tile 32x64. Fused epilogue per n-tile.
// ---------------------------------------------------------------------------
__global__ void __launch_bounds__(NTHREADS, 1)
mhmlp_main_kernel(const float* __restrict__ b2, float* __restrict__ out)
{
    extern __shared__ char smem[];
    const uint32_t sbase = smem_u32(smem);
    float* rowacc = (float*)(smem + OFF_ROWACC);

    const int tid  = threadIdx.x;
    const int lane = tid & 31;
    const int wid  = tid >> 5;
    const int wm   = wid >> 2;      // 0..3 : 32-row band
    const int wn   = wid & 3;       // 0..3 : 64-col band

    const int mt = blockIdx.x;      // 16 (fast dim -> head weights hot in L2)
    const int h  = blockIdx.y;      // 64
    const int m0 = mt * BM;

    if (tid < BM) rowacc[tid] = 0.f;

    const __half* __restrict__ Wh_h = g_Wh + (size_t)h * ND * NHID;
    const float4* __restrict__ pk_h = g_pk4 + (size_t)h * (NHID / 2);

    // ---- prologue: stage ALL of A (committed together with B chunk 0) ----
    #pragma unroll
    for (int i = 0; i < 16; i++) {               // 8192 segs of 16B
        int t = tid + i * NTHREADS;
        int r = t >> 6, s = t & 63;
        const void* src = g_Xh + (size_t)(m0 + r) * ND + s * 8;
        cp16(sbase + OFF_A + r * LDAF_B + s * 16, src);
    }

    auto stageB = [&](int cc) {
        const int nt = cc >> 3, kt = cc & 7, buf = cc % NSTAGE;
        #pragma unroll
        for (int i = 0; i < 4; i++) {            // 2048 segs of 16B
            int t = tid + i * NTHREADS;
            int r = t >> 5, s = t & 31;
            const void* src = Wh_h + (size_t)(kt * BK + r) * NHID + nt * BN + s * 8;
            uint32_t off = (uint32_t)(r * 512 + s * 16);
            cp16(sbase + OFF_B + buf * BSTG + (off ^ ((uint32_t)(r & 7) << 4)), src);
        }
        cp_commit();
    };

    stageB(0);          // group 0: A + B0
    stageB(1);          // group 1: B1

    float c[2][8][4];
    #pragma unroll
    for (int mi = 0; mi < 2; mi++)
        #pragma unroll
        for (int ni = 0; ni < 8; ni++)
            #pragma unroll
            for (int e = 0; e < 4; e++) c[mi][ni][e] = 0.f;
    float accrow[4] = {0.f, 0.f, 0.f, 0.f};

    for (int cc = 0; cc < NCHUNK; ++cc) {
        if (cc + 2 < NCHUNK) stageB(cc + 2); else cp_commit();
        asm volatile("cp.async.wait_group 2;" ::: "memory");
        __syncthreads();      // data for chunk cc visible to all warps

        const int kt = cc & 7;
        const uint32_t bB = sbase + OFF_B + (cc % NSTAGE) * BSTG;

        #pragma unroll
        for (int ks = 0; ks < 4; ks++) {
            uint32_t a[2][4];
            #pragma unroll
            for (int mi = 0; mi < 2; mi++) {
                int row = wm * 32 + mi * 16 + (lane & 15);
                uint32_t ad = sbase + OFF_A + row * LDAF_B
                            + (kt * BK + ks * 16 + (lane >> 4) * 8) * 2;
                asm volatile(
                    "ldmatrix.sync.aligned.m8n8.x4.shared.b16 {%0,%1,%2,%3}, [%4];"
                    : "=r"(a[mi][0]), "=r"(a[mi][1]), "=r"(a[mi][2]), "=r"(a[mi][3])
                    : "r"(ad));
            }
            uint32_t bf[8][2];
            #pragma unroll
            for (int np = 0; np < 4; np++) {
                int r = ks * 16 + (lane & 15);
                int n0 = wn * 64 + np * 16 + (lane >> 4) * 8;
                uint32_t off = (uint32_t)(r * 512 + n0 * 2);
                uint32_t ad = bB + (off ^ ((uint32_t)(r & 7) << 4));
                uint32_t r0, r1, r2, r3;
                asm volatile(
                    "ldmatrix.sync.aligned.m8n8.x4.trans.shared.b16 {%0,%1,%2,%3}, [%4];"
                    : "=r"(r0), "=r"(r1), "=r"(r2), "=r"(r3) : "r"(ad));
                bf[2 * np][0] = r0;     bf[2 * np][1] = r1;
                bf[2 * np + 1][0] = r2; bf[2 * np + 1][1] = r3;
            }
            #pragma unroll
            for (int mi = 0; mi < 2; mi++)
                #pragma unroll
                for (int ni = 0; ni < 8; ni++) {
                    asm volatile(
                        "mma.sync.aligned.m16n8k16.row.col.f32.f16.f16.f32 "
                        "{%0,%1,%2,%3}, {%4,%5,%6,%7}, {%8,%9}, {%0,%1,%2,%3};"
                        : "+f"(c[mi][ni][0]), "+f"(c[mi][ni][1]),
                          "+f"(c[mi][ni][2]), "+f"(c[mi][ni][3])
                        : "r"(a[mi][0]), "r"(a[mi][1]), "r"(a[mi][2]), "r"(a[mi][3]),
                          "r"(bf[ni][0]), "r"(bf[ni][1]));
                }
        }
        __syncthreads();      // all reads of buffer cc done before it is restaged

        if ((cc & 7) == 7) {    // K complete for this n-tile -> fused epilogue
            const int nt = cc >> 3;
            #pragma unroll
            for (int ni = 0; ni < 8; ni++) {
                // packed (b1,b1,W2,W2) for both column parities; mi-independent
                int cidx = nt * (BN / 2) + wn * 32 + ni * 4 + (lane & 3);
                float4 pk = __ldg(&pk_h[cidx]);
                #pragma unroll
                for (int mi = 0; mi < 2; mi++)
                    #pragma unroll
                    for (int e = 0; e < 4; e++) {
                        float bia = (e & 1) ? pk.y : pk.x;
                        float w2v = (e & 1) ? pk.w : pk.z;
                        float p = c[mi][ni][e] + bia;
                        accrow[mi * 2 + (e >> 1)] =
                            fmaf(lrelu(p), w2v, accrow[mi * 2 + (e >> 1)]);
                        c[mi][ni][e] = 0.f;
                    }
            }
        }
    }

    // reduce 4 lanes sharing each row, then across wn warps via smem atomics
    #pragma unroll
    for (int off = 1; off <= 2; off <<= 1)
        #pragma unroll
        for (int j = 0; j < 4; j++)
            accrow[j] += __shfl_xor_sync(0xffffffffu, accrow[j], off);

    if ((lane & 3) == 0) {
        #pragma unroll
        for (int mi = 0; mi < 2; mi++)
            #pragma unroll
            for (int e2 = 0; e2 < 2; e2++) {
                int row = wm * 32 + mi * 16 + e2 * 8 + (lane >> 2);
                atomicAdd(&rowacc[row], accrow[mi * 2 + e2]);
            }
    }
    __syncthreads();
    if (tid < BM) {
        float v = rowacc[tid] + __ldg(&b2[h]);
        out[(size_t)(m0 + tid) * NH + h] = lrelu(v);
    }
}

// ---------------------------------------------------------------------------
extern "C" void kernel_launch(void* const* d_in, const int* in_sizes, int n_in,
                              void* d_out, int out_size) {
    const float* x  = (const float*)d_in[0];   // [2048, 512]
    const float* W1 = (const float*)d_in[1];   // [64, 512, 2048]
    const float* b1 = (const float*)d_in[2];   // [64, 2048]
    const float* W2 = (const float*)d_in[3];   // [64, 2048]
    const float* b2 = (const float*)d_in[4];   // [64]
    float* out = (float*)d_out;                // [2048, 64]
    (void)in_sizes; (void)n_in; (void)out_size;

    cudaFuncSetAttribute(mhmlp_main_kernel,
                         cudaFuncAttributeMaxDynamicSharedMemorySize, SMEM_DYN);

    {
        size_t n4 = (size_t)NH * ND * NHID / 4;
        convert_w_kernel<<<(int)((n4 + 255) / 256), 256>>>(W1);
    }
    {
        size_t n4 = (size_t)NB * ND / 4;
        convert_x_kernel<<<(int)((n4 + 255) / 256), 256>>>(x);
    }
    {
        int n = NH * (NHID / 2);
        pack_kernel<<<(n + 255) / 256, 256>>>(b1, W2);
    }

    dim3 grid(NB / BM, NH);
    mhmlp_main_kernel<<<grid, NTHREADS, SMEM_DYN>>>(b2, out);
}